// round 14
// baseline (speedup 1.0000x reference)
#include <cuda_runtime.h>

#define HH 256
#define WW 256
#define NBLK 63
#define CAND 81
#define KSEL 16
#define NIMG 8
#define NW 10   // window cols per CTA (2 jb: dx 0..8 + jb 0..1)

__device__ __align__(16) float g_T[NIMG * NBLK * NBLK * 64];
__device__ __align__(16) float g_num[NIMG * HH * WW];
__device__ __align__(16) float g_W[NIMG * NBLK * NBLK];

// ---------------------------------------------------------------------------
// Compile-time DCT matrices -> FFMA immediates.
// ---------------------------------------------------------------------------
__device__ __host__ constexpr float COS32(int m) {
    m &= 63;
    if (m > 32) m = 64 - m;
    bool neg = false;
    if (m > 16) { neg = true; m = 32 - m; }
    float v = 0.0f;
    switch (m) {
        case 0:  v = 1.0f; break;
        case 1:  v = 0.99518472667219693f; break;
        case 2:  v = 0.98078528040323044f; break;
        case 3:  v = 0.95694033573220882f; break;
        case 4:  v = 0.92387953251128674f; break;
        case 5:  v = 0.88192126434835505f; break;
        case 6:  v = 0.83146961230254524f; break;
        case 7:  v = 0.77301045336273699f; break;
        case 8:  v = 0.70710678118654752f; break;
        case 9:  v = 0.63439328416364549f; break;
        case 10: v = 0.55557023301960218f; break;
        case 11: v = 0.47139673682599764f; break;
        case 12: v = 0.38268343236508984f; break;
        case 13: v = 0.29028467725446233f; break;
        case 14: v = 0.19509032201612828f; break;
        case 15: v = 0.09801714032956077f; break;
        default: v = 0.0f; break;
    }
    return neg ? -v : v;
}
__device__ __host__ constexpr float DKc(int k, int i) {
    return (k == 0) ? 0.25f : 0.35355339059327373f * COS32((2 * i + 1) * k);
}
__device__ __host__ constexpr float D8c(int k, int i) {
    return (k == 0) ? 0.35355339059327373f : 0.5f * COS32(2 * (2 * i + 1) * k);
}

// ---------------------------------------------------------------------------
__global__ void zero_kernel() {
    int idx = blockIdx.x * blockDim.x + threadIdx.x;
    const int N_NUM4 = NIMG * HH * WW / 4;
    const int N_W4   = NIMG * NBLK * NBLK / 4;
    if (idx < N_NUM4)
        ((float4*)g_num)[idx] = make_float4(0.f, 0.f, 0.f, 0.f);
    else if (idx < N_NUM4 + N_W4)
        ((float4*)g_W)[idx - N_NUM4] = make_float4(0.f, 0.f, 0.f, 0.f);
}

__global__ void nop_kernel() {}

// ---------------------------------------------------------------------------
// 8x8 DCT of every patch
// ---------------------------------------------------------------------------
__global__ void dct_kernel(const float* __restrict__ x) {
    __shared__ float sD[64];
    __shared__ float sp[4][64];
    __shared__ float st[4][64];
    int t = threadIdx.x;
    if (t < 64) {
        int k = t >> 3, i = t & 7;
        sD[t] = D8c(k, i);
    }
    int grp = t >> 6;
    int lt = t & 63;
    int pid = blockIdx.x * 4 + grp;
    bool valid = pid < NIMG * NBLK * NBLK;
    int img = 0, bi = 0, bj = 0;
    if (valid) {
        img = pid / (NBLK * NBLK);
        int r = pid % (NBLK * NBLK);
        bi = r / NBLK; bj = r % NBLK;
    }
    __syncthreads();
    if (valid) {
        int b = lt >> 3, c = lt & 7;
        float v = x[img * (HH * WW) + (bi * 4 + b) * WW + (bj * 4 + c)];
        sp[grp][lt] = fminf(fmaxf(v, 0.0f), 1.0f);
    }
    __syncthreads();
    if (valid) {
        int a = lt >> 3, c = lt & 7;
        float acc = 0.f;
#pragma unroll
        for (int b = 0; b < 8; b++) acc += sD[a * 8 + b] * sp[grp][b * 8 + c];
        st[grp][lt] = acc;
    }
    __syncthreads();
    if (valid) {
        int a = lt >> 3, d = lt & 7;
        float acc = 0.f;
#pragma unroll
        for (int c = 0; c < 8; c++) acc += st[grp][a * 8 + c] * sD[d * 8 + c];
        g_T[pid * 64 + lt] = acc;
    }
}

// ---------------------------------------------------------------------------
// Main pipeline: 256 threads = two 128-thread halves, ONE jb per half.
// u64 keys give a strict total order for top-16 (exact JAX tie semantics).
// ---------------------------------------------------------------------------
__global__ void __launch_bounds__(256, 6) bm3d_kernel() {
    __shared__ float nbT[9 * NW * 64];                      // 23040 B; front reused as GA/GB
    __shared__ float sD[64];
    __shared__ __align__(16) unsigned long long skey[2][82];  // [81] = max pad
    __shared__ int selOff[2][KSEL];
    __shared__ int selYs[2][KSEL];
    __shared__ int selXs[2][KSEL];
    __shared__ int snnz[2];

    int t = threadIdx.x;
    int img = blockIdx.x;
    int j0 = blockIdx.y * 2;
    int i = blockIdx.z;

    int half = t >> 7;
    int ht   = t & 127;
    int lane = t & 31;
    int hwarp = ht >> 5;
    int grpL = lane >> 3;
    int sub  = lane & 7;
    int p    = ht & 63;

    int j = j0 + half;
    bool active = j < NBLK;

    float* GA_h = nbT + half * 1024;
    float* GB_h = nbT + 2048 + half * 1024;

    if (t < 64) {
        int k = t >> 3, ii = t & 7;
        sD[t] = D8c(k, ii);
    }
    if (ht == 0) {
        snnz[half] = 0;
        skey[half][81] = 0xFFFFFFFFFFFFFFFFull;
    }

    // --- tile fill (9 x NW patch window) ---
    const float* Timg = g_T + img * (NBLK * NBLK * 64);
    for (int idx4 = t; idx4 < 9 * NW * 16; idx4 += 256) {
        int rs = idx4 >> 4;
        int p4 = (idx4 & 15) * 4;
        int r = rs / NW;
        int s = rs % NW;
        int ci = min(max(i - 4 + r, 0), NBLK - 1);
        int cj = min(max(j0 - 4 + s, 0), NBLK - 1);
        float4 v = *(const float4*)(Timg + (ci * NBLK + cj) * 64 + p4);
        *(float4*)(&nbT[(rs << 6) + p4]) = v;
    }
    __syncthreads();

    float* numImg = g_num + img * (HH * WW);
    float* Wimg   = g_W + img * (NBLK * NBLK);

    // --- candidate distances -> u64 keys ---
    if (active) {
        const float* rp = &nbT[((4 * NW + half + 4) << 6) + sub * 8];
        float4 rv0 = *(const float4*)(rp);
        float4 rv1 = *(const float4*)(rp + 4);
        for (int cb = hwarp * 4; cb < CAND; cb += 16) {
            int cid = min(cb + grpL, CAND - 1);
            int rr = cid / 9;
            int sc = half + (cid % 9);
            const float* cp = &nbT[((rr * NW + sc) << 6) + sub * 8];
            float4 cv0 = *(const float4*)(cp);
            float4 cv1 = *(const float4*)(cp + 4);
            float d0 = cv0.x - rv0.x, d1 = cv0.y - rv0.y;
            float acc = d0 * d0 + d1 * d1;
            d0 = cv0.z - rv0.z; d1 = cv0.w - rv0.w;
            acc += d0 * d0 + d1 * d1;
            d0 = cv1.x - rv1.x; d1 = cv1.y - rv1.y;
            acc += d0 * d0 + d1 * d1;
            d0 = cv1.z - rv1.z; d1 = cv1.w - rv1.w;
            acc += d0 * d0 + d1 * d1;
            acc += __shfl_xor_sync(0xffffffffu, acc, 1);
            acc += __shfl_xor_sync(0xffffffffu, acc, 2);
            acc += __shfl_xor_sync(0xffffffffu, acc, 4);
            if (sub == 0 && cb + grpL < CAND)
                skey[half][cid] =
                    ((unsigned long long)__float_as_uint(acc) << 32) | (unsigned)cid;
        }
    }
    __syncthreads();

    // --- rank-based top-16 via strict u64 total order ---
    if (active && ht < CAND) {
        const ulonglong2* ks2 = (const ulonglong2*)&skey[half][0];
        unsigned long long my = skey[half][ht];
        int rank = 0;
#pragma unroll
        for (int c2 = 0; c2 < 41; c2++) {
            ulonglong2 kp = ks2[c2];
            rank += (kp.x < my) ? 1 : 0;
            rank += (kp.y < my) ? 1 : 0;
        }
        if (rank < KSEL) {
            int rr = ht / 9;
            int dx = ht % 9;
            selOff[half][rank] = (rr * NW + half + dx) << 6;
            int ci = min(max(i - 4 + rr, 0), NBLK - 1);
            int cj = min(max(j - 4 + dx, 0), NBLK - 1);
            selYs[half][rank] = ci * 4;
            selXs[half][rank] = cj * 4;
        }
    }
    __syncthreads();

    // --- gather group into regs; even/odd sums (DCT16 symmetry) ---
    float s8[8], d8[8];
    if (active) {
        float g[16];
#pragma unroll
        for (int k = 0; k < 16; k++) g[k] = nbT[selOff[half][k] + p];
#pragma unroll
        for (int k = 0; k < 8; k++) {
            s8[k] = g[k] + g[15 - k];
            d8[k] = g[k] - g[15 - k];
        }
    }
    __syncthreads();   // all nbT reads done -> GA/GB alias region writable

    // --- forward DCT16 (immediates, even/odd) + threshold + nnz -> GA ---
    if (active) {
        int cnt = 0;
        if (ht < 64) {
#pragma unroll
            for (int q = 0; q < 8; q++) {
                float acc = 0.f;
#pragma unroll
                for (int k = 0; k < 8; k++)
                    acc += DKc(q, k) * ((q & 1) ? d8[k] : s8[k]);
                bool m = fabsf(acc) > 0.135f;
                cnt += m ? 1 : 0;
                GA_h[q * 64 + p] = m ? acc : 0.0f;
            }
        } else {
#pragma unroll
            for (int q = 8; q < 16; q++) {
                float acc = 0.f;
#pragma unroll
                for (int k = 0; k < 8; k++)
                    acc += DKc(q, k) * ((q & 1) ? d8[k] : s8[k]);
                bool m = fabsf(acc) > 0.135f;
                cnt += m ? 1 : 0;
                GA_h[q * 64 + p] = m ? acc : 0.0f;
            }
        }
        cnt = __reduce_add_sync(0xffffffffu, cnt);
        if (lane == 0) atomicAdd(&snnz[half], cnt);
    }
    __syncthreads();
    float wgt = 400.0f / fmaxf((float)snnz[half], 1.0f);

    // --- second DK apply (ref bug), even/odd -> GB ---
    if (active) {
        float g[16];
#pragma unroll
        for (int k = 0; k < 16; k++) g[k] = GA_h[k * 64 + p];
        float s2[8], d2[8];
#pragma unroll
        for (int k = 0; k < 8; k++) {
            s2[k] = g[k] + g[15 - k];
            d2[k] = g[k] - g[15 - k];
        }
        if (ht < 64) {
#pragma unroll
            for (int q = 0; q < 8; q++) {
                float acc = 0.f;
#pragma unroll
                for (int k = 0; k < 8; k++)
                    acc += DKc(q, k) * ((q & 1) ? d2[k] : s2[k]);
                GB_h[q * 64 + p] = acc;
            }
        } else {
#pragma unroll
            for (int q = 8; q < 16; q++) {
                float acc = 0.f;
#pragma unroll
                for (int k = 0; k < 8; k++)
                    acc += DKc(q, k) * ((q & 1) ? d2[k] : s2[k]);
                GB_h[q * 64 + p] = acc;
            }
        }
    }
    __syncthreads();

    // --- 2D inverse stage 1: GB rows -> GA (quarter-warp broadcast reads) ---
    if (active) {
        int hh = ht >> 6;
        int a = p >> 3, y = p & 7;
#pragma unroll
        for (int q = 0; q < 8; q++) {
            int k = hh * 8 + q;
            const float* gb = &GB_h[k * 64 + a * 8];
            float4 b0 = *(const float4*)(gb);
            float4 b1 = *(const float4*)(gb + 4);
            float acc = b0.x * sD[0 * 8 + y] + b0.y * sD[1 * 8 + y] +
                        b0.z * sD[2 * 8 + y] + b0.w * sD[3 * 8 + y] +
                        b1.x * sD[4 * 8 + y] + b1.y * sD[5 * 8 + y] +
                        b1.z * sD[6 * 8 + y] + b1.w * sD[7 * 8 + y];
            GA_h[k * 64 + p] = acc;
        }
    }
    __syncthreads();

    // --- 2D inverse stage 2 + quad scatter; quarter-warps share (k,qc)
    //     so GA reads are broadcast within each 8-lane group ---
    if (active) {
#pragma unroll
        for (int pass = 0; pass < 2; pass++) {
            int item = ht + pass * 128;
            int pair = item >> 3;            // 0..31: (k, qc)
            int b = item & 7;                // output row (varies within 8 lanes)
            int k = pair >> 1;
            int qc = (pair & 1) * 4;
            float o0 = 0.f, o1 = 0.f, o2 = 0.f, o3 = 0.f;
#pragma unroll
            for (int a = 0; a < 8; a++) {
                float dv = sD[a * 8 + b];
                float4 ga = *(const float4*)(&GA_h[k * 64 + a * 8 + qc]);
                o0 += dv * ga.x;
                o1 += dv * ga.y;
                o2 += dv * ga.z;
                o3 += dv * ga.w;
            }
            int row = selYs[half][k] + b;
            int col = selXs[half][k] + qc;
            float4 v = make_float4(wgt * o0, wgt * o1, wgt * o2, wgt * o3);
            atomicAdd((float4*)(numImg + row * WW + col), v);
        }
        if (ht < KSEL) {
            int ci = selYs[half][ht] >> 2;
            int cj = selXs[half][ht] >> 2;
            atomicAdd(&Wimg[ci * NBLK + cj], wgt);
        }
    }
}

// ---------------------------------------------------------------------------
// Final divide: cnt reconstructed from the per-origin weight map.
// ---------------------------------------------------------------------------
__global__ void div_kernel(float* __restrict__ out) {
    int idx = blockIdx.x * blockDim.x + threadIdx.x;
    int img = idx >> 16;
    int y = (idx >> 8) & 255;
    int x = idx & 255;
    const float* Wimg = g_W + img * (NBLK * NBLK);

    int ayh = min(NBLK - 1, y >> 2);
    int ayl = ayh - 1;
    bool vy = (ayl >= 0) && (ayl * 4 + 7 >= y);
    int axh = min(NBLK - 1, x >> 2);
    int axl = axh - 1;
    bool vx = (axl >= 0) && (axl * 4 + 7 >= x);

    float cnt = Wimg[ayh * NBLK + axh];
    if (vx) cnt += Wimg[ayh * NBLK + axl];
    if (vy) cnt += Wimg[ayl * NBLK + axh];
    if (vy && vx) cnt += Wimg[ayl * NBLK + axl];

    out[idx] = g_num[idx] / fmaxf(cnt, 1e-8f);
}

// ---------------------------------------------------------------------------
extern "C" void kernel_launch(void* const* d_in, const int* in_sizes, int n_in,
                              void* d_out, int out_size) {
    const float* x = (const float*)d_in[0];
    (void)in_sizes; (void)n_in; (void)out_size;

    zero_kernel<<<544, 256>>>();                                 // idx 0
    dct_kernel<<<(NIMG * NBLK * NBLK + 3) / 4, 256>>>(x);        // idx 1
    nop_kernel<<<1, 32>>>();                                     // idx 2
    bm3d_kernel<<<dim3(NIMG, 32, NBLK), 256>>>();                // idx 3 <- ncu capture slot
    div_kernel<<<2048, 256>>>((float*)d_out);                    // idx 4
}

// round 15
// speedup vs baseline: 1.0022x; 1.0022x over previous
#include <cuda_runtime.h>

#define HH 256
#define WW 256
#define NBLK 63
#define CAND 81
#define KSEL 16
#define NIMG 8
#define NW 10   // window cols per CTA (2 jb: dx 0..8 + jb 0..1)

__device__ __align__(16) float g_T[NIMG * NBLK * NBLK * 64];
__device__ __align__(16) float g_num[NIMG * HH * WW];
__device__ __align__(16) float g_W[NIMG * NBLK * NBLK];

// ---------------------------------------------------------------------------
// Compile-time DCT matrices -> FFMA immediates.
// ---------------------------------------------------------------------------
__device__ __host__ constexpr float COS32(int m) {
    m &= 63;
    if (m > 32) m = 64 - m;
    bool neg = false;
    if (m > 16) { neg = true; m = 32 - m; }
    float v = 0.0f;
    switch (m) {
        case 0:  v = 1.0f; break;
        case 1:  v = 0.99518472667219693f; break;
        case 2:  v = 0.98078528040323044f; break;
        case 3:  v = 0.95694033573220882f; break;
        case 4:  v = 0.92387953251128674f; break;
        case 5:  v = 0.88192126434835505f; break;
        case 6:  v = 0.83146961230254524f; break;
        case 7:  v = 0.77301045336273699f; break;
        case 8:  v = 0.70710678118654752f; break;
        case 9:  v = 0.63439328416364549f; break;
        case 10: v = 0.55557023301960218f; break;
        case 11: v = 0.47139673682599764f; break;
        case 12: v = 0.38268343236508984f; break;
        case 13: v = 0.29028467725446233f; break;
        case 14: v = 0.19509032201612828f; break;
        case 15: v = 0.09801714032956077f; break;
        default: v = 0.0f; break;
    }
    return neg ? -v : v;
}
__device__ __host__ constexpr float DKc(int k, int i) {
    return (k == 0) ? 0.25f : 0.35355339059327373f * COS32((2 * i + 1) * k);
}
__device__ __host__ constexpr float D8c(int k, int i) {
    return (k == 0) ? 0.35355339059327373f : 0.5f * COS32(2 * (2 * i + 1) * k);
}

// ---------------------------------------------------------------------------
__global__ void zero_kernel() {
    int idx = blockIdx.x * blockDim.x + threadIdx.x;
    const int N_NUM4 = NIMG * HH * WW / 4;
    const int N_W4   = NIMG * NBLK * NBLK / 4;
    if (idx < N_NUM4)
        ((float4*)g_num)[idx] = make_float4(0.f, 0.f, 0.f, 0.f);
    else if (idx < N_NUM4 + N_W4)
        ((float4*)g_W)[idx - N_NUM4] = make_float4(0.f, 0.f, 0.f, 0.f);
}

__global__ void nop_kernel() {}

// ---------------------------------------------------------------------------
// 8x8 DCT of every patch
// ---------------------------------------------------------------------------
__global__ void dct_kernel(const float* __restrict__ x) {
    __shared__ float sD[64];
    __shared__ float sp[4][64];
    __shared__ float st[4][64];
    int t = threadIdx.x;
    if (t < 64) {
        int k = t >> 3, i = t & 7;
        sD[t] = D8c(k, i);
    }
    int grp = t >> 6;
    int lt = t & 63;
    int pid = blockIdx.x * 4 + grp;
    bool valid = pid < NIMG * NBLK * NBLK;
    int img = 0, bi = 0, bj = 0;
    if (valid) {
        img = pid / (NBLK * NBLK);
        int r = pid % (NBLK * NBLK);
        bi = r / NBLK; bj = r % NBLK;
    }
    __syncthreads();
    if (valid) {
        int b = lt >> 3, c = lt & 7;
        float v = x[img * (HH * WW) + (bi * 4 + b) * WW + (bj * 4 + c)];
        sp[grp][lt] = fminf(fmaxf(v, 0.0f), 1.0f);
    }
    __syncthreads();
    if (valid) {
        int a = lt >> 3, c = lt & 7;
        float acc = 0.f;
#pragma unroll
        for (int b = 0; b < 8; b++) acc += sD[a * 8 + b] * sp[grp][b * 8 + c];
        st[grp][lt] = acc;
    }
    __syncthreads();
    if (valid) {
        int a = lt >> 3, d = lt & 7;
        float acc = 0.f;
#pragma unroll
        for (int c = 0; c < 8; c++) acc += st[grp][a * 8 + c] * sD[d * 8 + c];
        g_T[pid * 64 + lt] = acc;
    }
}

// ---------------------------------------------------------------------------
// Main pipeline: 256 threads = two 128-thread halves, ONE jb per half.
// u64 keys give a strict total order for top-16 (exact JAX tie semantics).
// ---------------------------------------------------------------------------
__global__ void __launch_bounds__(256, 6) bm3d_kernel() {
    __shared__ float nbT[9 * NW * 64];                      // 23040 B; front reused as GA/GB
    __shared__ float sD[64];
    __shared__ __align__(16) unsigned long long skey[2][82];  // [81] = max pad
    __shared__ int selOff[2][KSEL];
    __shared__ int selYs[2][KSEL];
    __shared__ int selXs[2][KSEL];
    __shared__ int snnz[2];

    int t = threadIdx.x;
    int img = blockIdx.x;
    int j0 = blockIdx.y * 2;
    int i = blockIdx.z;

    int half = t >> 7;
    int ht   = t & 127;
    int lane = t & 31;
    int hwarp = ht >> 5;
    int grpL = lane >> 3;
    int sub  = lane & 7;
    int p    = ht & 63;

    int j = j0 + half;
    bool active = j < NBLK;

    float* GA_h = nbT + half * 1024;
    float* GB_h = nbT + 2048 + half * 1024;

    if (t < 64) {
        int k = t >> 3, ii = t & 7;
        sD[t] = D8c(k, ii);
    }
    if (ht == 0) {
        snnz[half] = 0;
        skey[half][81] = 0xFFFFFFFFFFFFFFFFull;
    }

    // --- tile fill (9 x NW patch window) ---
    const float* Timg = g_T + img * (NBLK * NBLK * 64);
    for (int idx4 = t; idx4 < 9 * NW * 16; idx4 += 256) {
        int rs = idx4 >> 4;
        int p4 = (idx4 & 15) * 4;
        int r = rs / NW;
        int s = rs % NW;
        int ci = min(max(i - 4 + r, 0), NBLK - 1);
        int cj = min(max(j0 - 4 + s, 0), NBLK - 1);
        float4 v = *(const float4*)(Timg + (ci * NBLK + cj) * 64 + p4);
        *(float4*)(&nbT[(rs << 6) + p4]) = v;
    }
    __syncthreads();

    float* numImg = g_num + img * (HH * WW);
    float* Wimg   = g_W + img * (NBLK * NBLK);

    // --- candidate distances -> u64 keys ---
    if (active) {
        const float* rp = &nbT[((4 * NW + half + 4) << 6) + sub * 8];
        float4 rv0 = *(const float4*)(rp);
        float4 rv1 = *(const float4*)(rp + 4);
        for (int cb = hwarp * 4; cb < CAND; cb += 16) {
            int cid = min(cb + grpL, CAND - 1);
            int rr = cid / 9;
            int sc = half + (cid % 9);
            const float* cp = &nbT[((rr * NW + sc) << 6) + sub * 8];
            float4 cv0 = *(const float4*)(cp);
            float4 cv1 = *(const float4*)(cp + 4);
            float d0 = cv0.x - rv0.x, d1 = cv0.y - rv0.y;
            float acc = d0 * d0 + d1 * d1;
            d0 = cv0.z - rv0.z; d1 = cv0.w - rv0.w;
            acc += d0 * d0 + d1 * d1;
            d0 = cv1.x - rv1.x; d1 = cv1.y - rv1.y;
            acc += d0 * d0 + d1 * d1;
            d0 = cv1.z - rv1.z; d1 = cv1.w - rv1.w;
            acc += d0 * d0 + d1 * d1;
            acc += __shfl_xor_sync(0xffffffffu, acc, 1);
            acc += __shfl_xor_sync(0xffffffffu, acc, 2);
            acc += __shfl_xor_sync(0xffffffffu, acc, 4);
            if (sub == 0 && cb + grpL < CAND)
                skey[half][cid] =
                    ((unsigned long long)__float_as_uint(acc) << 32) | (unsigned)cid;
        }
    }
    __syncthreads();

    // --- rank-based top-16 via strict u64 total order ---
    if (active && ht < CAND) {
        const ulonglong2* ks2 = (const ulonglong2*)&skey[half][0];
        unsigned long long my = skey[half][ht];
        int rank = 0;
#pragma unroll
        for (int c2 = 0; c2 < 41; c2++) {
            ulonglong2 kp = ks2[c2];
            rank += (kp.x < my) ? 1 : 0;
            rank += (kp.y < my) ? 1 : 0;
        }
        if (rank < KSEL) {
            int rr = ht / 9;
            int dx = ht % 9;
            selOff[half][rank] = (rr * NW + half + dx) << 6;
            int ci = min(max(i - 4 + rr, 0), NBLK - 1);
            int cj = min(max(j - 4 + dx, 0), NBLK - 1);
            selYs[half][rank] = ci * 4;
            selXs[half][rank] = cj * 4;
        }
    }
    __syncthreads();

    // --- gather group into regs; even/odd sums (DCT16 symmetry) ---
    float s8[8], d8[8];
    if (active) {
        float g[16];
#pragma unroll
        for (int k = 0; k < 16; k++) g[k] = nbT[selOff[half][k] + p];
#pragma unroll
        for (int k = 0; k < 8; k++) {
            s8[k] = g[k] + g[15 - k];
            d8[k] = g[k] - g[15 - k];
        }
    }
    __syncthreads();   // all nbT reads done -> GA/GB alias region writable

    // --- forward DCT16 (immediates, even/odd) + threshold + nnz -> GA ---
    if (active) {
        int cnt = 0;
        if (ht < 64) {
#pragma unroll
            for (int q = 0; q < 8; q++) {
                float acc = 0.f;
#pragma unroll
                for (int k = 0; k < 8; k++)
                    acc += DKc(q, k) * ((q & 1) ? d8[k] : s8[k]);
                bool m = fabsf(acc) > 0.135f;
                cnt += m ? 1 : 0;
                GA_h[q * 64 + p] = m ? acc : 0.0f;
            }
        } else {
#pragma unroll
            for (int q = 8; q < 16; q++) {
                float acc = 0.f;
#pragma unroll
                for (int k = 0; k < 8; k++)
                    acc += DKc(q, k) * ((q & 1) ? d8[k] : s8[k]);
                bool m = fabsf(acc) > 0.135f;
                cnt += m ? 1 : 0;
                GA_h[q * 64 + p] = m ? acc : 0.0f;
            }
        }
        cnt = __reduce_add_sync(0xffffffffu, cnt);
        if (lane == 0) atomicAdd(&snnz[half], cnt);
    }
    __syncthreads();
    float wgt = 400.0f / fmaxf((float)snnz[half], 1.0f);

    // --- second DK apply (ref bug), even/odd -> GB ---
    if (active) {
        float g[16];
#pragma unroll
        for (int k = 0; k < 16; k++) g[k] = GA_h[k * 64 + p];
        float s2[8], d2[8];
#pragma unroll
        for (int k = 0; k < 8; k++) {
            s2[k] = g[k] + g[15 - k];
            d2[k] = g[k] - g[15 - k];
        }
        if (ht < 64) {
#pragma unroll
            for (int q = 0; q < 8; q++) {
                float acc = 0.f;
#pragma unroll
                for (int k = 0; k < 8; k++)
                    acc += DKc(q, k) * ((q & 1) ? d2[k] : s2[k]);
                GB_h[q * 64 + p] = acc;
            }
        } else {
#pragma unroll
            for (int q = 8; q < 16; q++) {
                float acc = 0.f;
#pragma unroll
                for (int k = 0; k < 8; k++)
                    acc += DKc(q, k) * ((q & 1) ? d2[k] : s2[k]);
                GB_h[q * 64 + p] = acc;
            }
        }
    }
    __syncthreads();

    // --- 2D inverse stage 1: GB rows -> GA (quarter-warp broadcast reads) ---
    if (active) {
        int hh = ht >> 6;
        int a = p >> 3, y = p & 7;
#pragma unroll
        for (int q = 0; q < 8; q++) {
            int k = hh * 8 + q;
            const float* gb = &GB_h[k * 64 + a * 8];
            float4 b0 = *(const float4*)(gb);
            float4 b1 = *(const float4*)(gb + 4);
            float acc = b0.x * sD[0 * 8 + y] + b0.y * sD[1 * 8 + y] +
                        b0.z * sD[2 * 8 + y] + b0.w * sD[3 * 8 + y] +
                        b1.x * sD[4 * 8 + y] + b1.y * sD[5 * 8 + y] +
                        b1.z * sD[6 * 8 + y] + b1.w * sD[7 * 8 + y];
            GA_h[k * 64 + p] = acc;
        }
    }
    __syncthreads();

    // --- 2D inverse stage 2 + quad scatter; quarter-warps share (k,qc)
    //     so GA reads are broadcast within each 8-lane group ---
    if (active) {
#pragma unroll
        for (int pass = 0; pass < 2; pass++) {
            int item = ht + pass * 128;
            int pair = item >> 3;            // 0..31: (k, qc)
            int b = item & 7;                // output row (varies within 8 lanes)
            int k = pair >> 1;
            int qc = (pair & 1) * 4;
            float o0 = 0.f, o1 = 0.f, o2 = 0.f, o3 = 0.f;
#pragma unroll
            for (int a = 0; a < 8; a++) {
                float dv = sD[a * 8 + b];
                float4 ga = *(const float4*)(&GA_h[k * 64 + a * 8 + qc]);
                o0 += dv * ga.x;
                o1 += dv * ga.y;
                o2 += dv * ga.z;
                o3 += dv * ga.w;
            }
            int row = selYs[half][k] + b;
            int col = selXs[half][k] + qc;
            float4 v = make_float4(wgt * o0, wgt * o1, wgt * o2, wgt * o3);
            atomicAdd((float4*)(numImg + row * WW + col), v);
        }
        if (ht < KSEL) {
            int ci = selYs[half][ht] >> 2;
            int cj = selXs[half][ht] >> 2;
            atomicAdd(&Wimg[ci * NBLK + cj], wgt);
        }
    }
}

// ---------------------------------------------------------------------------
// Final divide: cnt reconstructed from the per-origin weight map.
// ---------------------------------------------------------------------------
__global__ void div_kernel(float* __restrict__ out) {
    int idx = blockIdx.x * blockDim.x + threadIdx.x;
    int img = idx >> 16;
    int y = (idx >> 8) & 255;
    int x = idx & 255;
    const float* Wimg = g_W + img * (NBLK * NBLK);

    int ayh = min(NBLK - 1, y >> 2);
    int ayl = ayh - 1;
    bool vy = (ayl >= 0) && (ayl * 4 + 7 >= y);
    int axh = min(NBLK - 1, x >> 2);
    int axl = axh - 1;
    bool vx = (axl >= 0) && (axl * 4 + 7 >= x);

    float cnt = Wimg[ayh * NBLK + axh];
    if (vx) cnt += Wimg[ayh * NBLK + axl];
    if (vy) cnt += Wimg[ayl * NBLK + axh];
    if (vy && vx) cnt += Wimg[ayl * NBLK + axl];

    out[idx] = g_num[idx] / fmaxf(cnt, 1e-8f);
}

// ---------------------------------------------------------------------------
extern "C" void kernel_launch(void* const* d_in, const int* in_sizes, int n_in,
                              void* d_out, int out_size) {
    const float* x = (const float*)d_in[0];
    (void)in_sizes; (void)n_in; (void)out_size;

    zero_kernel<<<544, 256>>>();                                 // idx 0
    dct_kernel<<<(NIMG * NBLK * NBLK + 3) / 4, 256>>>(x);        // idx 1
    nop_kernel<<<1, 32>>>();                                     // idx 2
    bm3d_kernel<<<dim3(NIMG, 32, NBLK), 256>>>();                // idx 3 <- ncu capture slot
    div_kernel<<<2048, 256>>>((float*)d_out);                    // idx 4
}

// round 16
// speedup vs baseline: 1.0456x; 1.0433x over previous
#include <cuda_runtime.h>

#define HH 256
#define WW 256
#define NBLK 63
#define CAND 81
#define KSEL 16
#define NIMG 8
#define NW 10   // window cols per CTA (2 jb: dx 0..8 + jb 0..1)

__device__ __align__(16) float g_T[NIMG * NBLK * NBLK * 64];
__device__ __align__(16) float g_num[NIMG * HH * WW];
__device__ __align__(16) float g_W[NIMG * NBLK * NBLK];

// ---------------------------------------------------------------------------
// Compile-time DCT matrices -> FFMA immediates.
// ---------------------------------------------------------------------------
__device__ __host__ constexpr float COS32(int m) {
    m &= 63;
    if (m > 32) m = 64 - m;
    bool neg = false;
    if (m > 16) { neg = true; m = 32 - m; }
    float v = 0.0f;
    switch (m) {
        case 0:  v = 1.0f; break;
        case 1:  v = 0.99518472667219693f; break;
        case 2:  v = 0.98078528040323044f; break;
        case 3:  v = 0.95694033573220882f; break;
        case 4:  v = 0.92387953251128674f; break;
        case 5:  v = 0.88192126434835505f; break;
        case 6:  v = 0.83146961230254524f; break;
        case 7:  v = 0.77301045336273699f; break;
        case 8:  v = 0.70710678118654752f; break;
        case 9:  v = 0.63439328416364549f; break;
        case 10: v = 0.55557023301960218f; break;
        case 11: v = 0.47139673682599764f; break;
        case 12: v = 0.38268343236508984f; break;
        case 13: v = 0.29028467725446233f; break;
        case 14: v = 0.19509032201612828f; break;
        case 15: v = 0.09801714032956077f; break;
        default: v = 0.0f; break;
    }
    return neg ? -v : v;
}
__device__ __host__ constexpr float DKc(int k, int i) {
    return (k == 0) ? 0.25f : 0.35355339059327373f * COS32((2 * i + 1) * k);
}
__device__ __host__ constexpr float D8c(int k, int i) {
    return (k == 0) ? 0.35355339059327373f : 0.5f * COS32(2 * (2 * i + 1) * k);
}

// ---------------------------------------------------------------------------
__global__ void zero_kernel() {
    int idx = blockIdx.x * blockDim.x + threadIdx.x;
    const int N_NUM4 = NIMG * HH * WW / 4;
    const int N_W4   = NIMG * NBLK * NBLK / 4;
    if (idx < N_NUM4)
        ((float4*)g_num)[idx] = make_float4(0.f, 0.f, 0.f, 0.f);
    else if (idx < N_NUM4 + N_W4)
        ((float4*)g_W)[idx - N_NUM4] = make_float4(0.f, 0.f, 0.f, 0.f);
}

__global__ void nop_kernel() {}

// ---------------------------------------------------------------------------
// 8x8 DCT of every patch
// ---------------------------------------------------------------------------
__global__ void dct_kernel(const float* __restrict__ x) {
    __shared__ float sD[64];
    __shared__ float sp[4][64];
    __shared__ float st[4][64];
    int t = threadIdx.x;
    if (t < 64) {
        int k = t >> 3, i = t & 7;
        sD[t] = D8c(k, i);
    }
    int grp = t >> 6;
    int lt = t & 63;
    int pid = blockIdx.x * 4 + grp;
    bool valid = pid < NIMG * NBLK * NBLK;
    int img = 0, bi = 0, bj = 0;
    if (valid) {
        img = pid / (NBLK * NBLK);
        int r = pid % (NBLK * NBLK);
        bi = r / NBLK; bj = r % NBLK;
    }
    __syncthreads();
    if (valid) {
        int b = lt >> 3, c = lt & 7;
        float v = x[img * (HH * WW) + (bi * 4 + b) * WW + (bj * 4 + c)];
        sp[grp][lt] = fminf(fmaxf(v, 0.0f), 1.0f);
    }
    __syncthreads();
    if (valid) {
        int a = lt >> 3, c = lt & 7;
        float acc = 0.f;
#pragma unroll
        for (int b = 0; b < 8; b++) acc += sD[a * 8 + b] * sp[grp][b * 8 + c];
        st[grp][lt] = acc;
    }
    __syncthreads();
    if (valid) {
        int a = lt >> 3, d = lt & 7;
        float acc = 0.f;
#pragma unroll
        for (int c = 0; c < 8; c++) acc += st[grp][a * 8 + c] * sD[d * 8 + c];
        g_T[pid * 64 + lt] = acc;
    }
}

// ---------------------------------------------------------------------------
// Main pipeline: 256 threads = two 128-thread halves, ONE jb per half.
// u64 keys = strict total order (exact JAX tie semantics, no duplicate ranks).
// Stage-2 scatter uses R13's coalesced lane->quad mapping.
// ---------------------------------------------------------------------------
__global__ void __launch_bounds__(256, 6) bm3d_kernel() {
    __shared__ float nbT[9 * NW * 64];                        // 23040 B; front reused as GA/GB
    __shared__ float sD[64];
    __shared__ __align__(16) unsigned long long skey[2][82];  // [81] = max pad
    __shared__ int selOff[2][KSEL];
    __shared__ int selYs[2][KSEL];
    __shared__ int selXs[2][KSEL];
    __shared__ int snnz[2];

    int t = threadIdx.x;
    int img = blockIdx.x;
    int j0 = blockIdx.y * 2;
    int i = blockIdx.z;

    int half = t >> 7;
    int ht   = t & 127;
    int lane = t & 31;
    int hwarp = ht >> 5;
    int grpL = lane >> 3;
    int sub  = lane & 7;
    int p    = ht & 63;

    int j = j0 + half;
    bool active = j < NBLK;

    float* GA_h = nbT + half * 1024;
    float* GB_h = nbT + 2048 + half * 1024;

    if (t < 64) {
        int k = t >> 3, ii = t & 7;
        sD[t] = D8c(k, ii);
    }
    if (ht == 0) {
        snnz[half] = 0;
        skey[half][81] = 0xFFFFFFFFFFFFFFFFull;
    }

    // --- tile fill (9 x NW patch window) ---
    const float* Timg = g_T + img * (NBLK * NBLK * 64);
    for (int idx4 = t; idx4 < 9 * NW * 16; idx4 += 256) {
        int rs = idx4 >> 4;
        int p4 = (idx4 & 15) * 4;
        int r = rs / NW;
        int s = rs % NW;
        int ci = min(max(i - 4 + r, 0), NBLK - 1);
        int cj = min(max(j0 - 4 + s, 0), NBLK - 1);
        float4 v = *(const float4*)(Timg + (ci * NBLK + cj) * 64 + p4);
        *(float4*)(&nbT[(rs << 6) + p4]) = v;
    }
    __syncthreads();

    float* numImg = g_num + img * (HH * WW);
    float* Wimg   = g_W + img * (NBLK * NBLK);

    // --- candidate distances -> u64 keys ---
    if (active) {
        const float* rp = &nbT[((4 * NW + half + 4) << 6) + sub * 8];
        float4 rv0 = *(const float4*)(rp);
        float4 rv1 = *(const float4*)(rp + 4);
        for (int cb = hwarp * 4; cb < CAND; cb += 16) {
            int cid = min(cb + grpL, CAND - 1);
            int rr = cid / 9;
            int sc = half + (cid % 9);
            const float* cp = &nbT[((rr * NW + sc) << 6) + sub * 8];
            float4 cv0 = *(const float4*)(cp);
            float4 cv1 = *(const float4*)(cp + 4);
            float d0 = cv0.x - rv0.x, d1 = cv0.y - rv0.y;
            float acc = d0 * d0 + d1 * d1;
            d0 = cv0.z - rv0.z; d1 = cv0.w - rv0.w;
            acc += d0 * d0 + d1 * d1;
            d0 = cv1.x - rv1.x; d1 = cv1.y - rv1.y;
            acc += d0 * d0 + d1 * d1;
            d0 = cv1.z - rv1.z; d1 = cv1.w - rv1.w;
            acc += d0 * d0 + d1 * d1;
            acc += __shfl_xor_sync(0xffffffffu, acc, 1);
            acc += __shfl_xor_sync(0xffffffffu, acc, 2);
            acc += __shfl_xor_sync(0xffffffffu, acc, 4);
            if (sub == 0 && cb + grpL < CAND)
                skey[half][cid] =
                    ((unsigned long long)__float_as_uint(acc) << 32) | (unsigned)cid;
        }
    }
    __syncthreads();

    // --- rank-based top-16 via strict u64 total order ---
    if (active && ht < CAND) {
        const ulonglong2* ks2 = (const ulonglong2*)&skey[half][0];
        unsigned long long my = skey[half][ht];
        int rank = 0;
#pragma unroll
        for (int c2 = 0; c2 < 41; c2++) {
            ulonglong2 kp = ks2[c2];
            rank += (kp.x < my) ? 1 : 0;
            rank += (kp.y < my) ? 1 : 0;
        }
        if (rank < KSEL) {
            int rr = ht / 9;
            int dx = ht % 9;
            selOff[half][rank] = (rr * NW + half + dx) << 6;
            int ci = min(max(i - 4 + rr, 0), NBLK - 1);
            int cj = min(max(j - 4 + dx, 0), NBLK - 1);
            selYs[half][rank] = ci * 4;
            selXs[half][rank] = cj * 4;
        }
    }
    __syncthreads();

    // --- gather group into regs; even/odd sums (DCT16 symmetry) ---
    float s8[8], d8[8];
    if (active) {
        float g[16];
#pragma unroll
        for (int k = 0; k < 16; k++) g[k] = nbT[selOff[half][k] + p];
#pragma unroll
        for (int k = 0; k < 8; k++) {
            s8[k] = g[k] + g[15 - k];
            d8[k] = g[k] - g[15 - k];
        }
    }
    __syncthreads();   // all nbT reads done -> GA/GB alias region writable

    // --- forward DCT16 (immediates, even/odd) + threshold + nnz -> GA ---
    if (active) {
        int cnt = 0;
        if (ht < 64) {
#pragma unroll
            for (int q = 0; q < 8; q++) {
                float acc = 0.f;
#pragma unroll
                for (int k = 0; k < 8; k++)
                    acc += DKc(q, k) * ((q & 1) ? d8[k] : s8[k]);
                bool m = fabsf(acc) > 0.135f;
                cnt += m ? 1 : 0;
                GA_h[q * 64 + p] = m ? acc : 0.0f;
            }
        } else {
#pragma unroll
            for (int q = 8; q < 16; q++) {
                float acc = 0.f;
#pragma unroll
                for (int k = 0; k < 8; k++)
                    acc += DKc(q, k) * ((q & 1) ? d8[k] : s8[k]);
                bool m = fabsf(acc) > 0.135f;
                cnt += m ? 1 : 0;
                GA_h[q * 64 + p] = m ? acc : 0.0f;
            }
        }
        cnt = __reduce_add_sync(0xffffffffu, cnt);
        if (lane == 0) atomicAdd(&snnz[half], cnt);
    }
    __syncthreads();
    float wgt = 400.0f / fmaxf((float)snnz[half], 1.0f);

    // --- second DK apply (ref bug), even/odd -> GB ---
    if (active) {
        float g[16];
#pragma unroll
        for (int k = 0; k < 16; k++) g[k] = GA_h[k * 64 + p];
        float s2[8], d2[8];
#pragma unroll
        for (int k = 0; k < 8; k++) {
            s2[k] = g[k] + g[15 - k];
            d2[k] = g[k] - g[15 - k];
        }
        if (ht < 64) {
#pragma unroll
            for (int q = 0; q < 8; q++) {
                float acc = 0.f;
#pragma unroll
                for (int k = 0; k < 8; k++)
                    acc += DKc(q, k) * ((q & 1) ? d2[k] : s2[k]);
                GB_h[q * 64 + p] = acc;
            }
        } else {
#pragma unroll
            for (int q = 8; q < 16; q++) {
                float acc = 0.f;
#pragma unroll
                for (int k = 0; k < 8; k++)
                    acc += DKc(q, k) * ((q & 1) ? d2[k] : s2[k]);
                GB_h[q * 64 + p] = acc;
            }
        }
    }
    __syncthreads();

    // --- 2D inverse stage 1: GB rows -> GA ---
    if (active) {
        int hh = ht >> 6;
        int a = p >> 3, y = p & 7;
#pragma unroll
        for (int q = 0; q < 8; q++) {
            int k = hh * 8 + q;
            const float* gb = &GB_h[k * 64 + a * 8];
            float4 b0 = *(const float4*)(gb);
            float4 b1 = *(const float4*)(gb + 4);
            float acc = b0.x * sD[0 * 8 + y] + b0.y * sD[1 * 8 + y] +
                        b0.z * sD[2 * 8 + y] + b0.w * sD[3 * 8 + y] +
                        b1.x * sD[4 * 8 + y] + b1.y * sD[5 * 8 + y] +
                        b1.z * sD[6 * 8 + y] + b1.w * sD[7 * 8 + y];
            GA_h[k * 64 + p] = acc;
        }
    }
    __syncthreads();

    // --- 2D inverse stage 2 + quad scatter (R13 coalesced mapping) ---
    if (active) {
        for (int item = ht; item < 256; item += 128) {
            int k = item >> 4;
            int rem = item & 15;
            int b = rem >> 1;
            int qc = (rem & 1) * 4;
            float o0 = 0.f, o1 = 0.f, o2 = 0.f, o3 = 0.f;
#pragma unroll
            for (int a = 0; a < 8; a++) {
                float dv = sD[a * 8 + b];
                float4 ga = *(const float4*)(&GA_h[k * 64 + a * 8 + qc]);
                o0 += dv * ga.x;
                o1 += dv * ga.y;
                o2 += dv * ga.z;
                o3 += dv * ga.w;
            }
            int row = selYs[half][k] + b;
            int col = selXs[half][k] + qc;
            float4 v = make_float4(wgt * o0, wgt * o1, wgt * o2, wgt * o3);
            atomicAdd((float4*)(numImg + row * WW + col), v);
        }
        if (ht < KSEL) {
            int ci = selYs[half][ht] >> 2;
            int cj = selXs[half][ht] >> 2;
            atomicAdd(&Wimg[ci * NBLK + cj], wgt);
        }
    }
}

// ---------------------------------------------------------------------------
// Final divide: cnt reconstructed from the per-origin weight map.
// ---------------------------------------------------------------------------
__global__ void div_kernel(float* __restrict__ out) {
    int idx = blockIdx.x * blockDim.x + threadIdx.x;
    int img = idx >> 16;
    int y = (idx >> 8) & 255;
    int x = idx & 255;
    const float* Wimg = g_W + img * (NBLK * NBLK);

    int ayh = min(NBLK - 1, y >> 2);
    int ayl = ayh - 1;
    bool vy = (ayl >= 0) && (ayl * 4 + 7 >= y);
    int axh = min(NBLK - 1, x >> 2);
    int axl = axh - 1;
    bool vx = (axl >= 0) && (axl * 4 + 7 >= x);

    float cnt = Wimg[ayh * NBLK + axh];
    if (vx) cnt += Wimg[ayh * NBLK + axl];
    if (vy) cnt += Wimg[ayl * NBLK + axh];
    if (vy && vx) cnt += Wimg[ayl * NBLK + axl];

    out[idx] = g_num[idx] / fmaxf(cnt, 1e-8f);
}

// ---------------------------------------------------------------------------
extern "C" void kernel_launch(void* const* d_in, const int* in_sizes, int n_in,
                              void* d_out, int out_size) {
    const float* x = (const float*)d_in[0];
    (void)in_sizes; (void)n_in; (void)out_size;

    zero_kernel<<<544, 256>>>();                                 // idx 0
    dct_kernel<<<(NIMG * NBLK * NBLK + 3) / 4, 256>>>(x);        // idx 1
    nop_kernel<<<1, 32>>>();                                     // idx 2
    bm3d_kernel<<<dim3(NIMG, 32, NBLK), 256>>>();                // idx 3 <- ncu capture slot
    div_kernel<<<2048, 256>>>((float*)d_out);                    // idx 4
}